// round 15
// baseline (speedup 1.0000x reference)
#include <cuda_runtime.h>
#include <cuda_fp16.h>
#include <math.h>

#define NN 8192
#define NE 65536

// ---- folded normalization constants ----
#define INV_SQRT10 0.3162277660168379f
#define INV_SQRT8  0.3535533905932738f
#define S0    0.0220970869120796f
#define SA1   0.0220970869120796f
#define SB1   0.0255155128118852f
#define SC1   0.0180421959121758f
#define SD1   0.0360843918243516f
#define SDV1  0.0255155128118852f
#define SA2   0.0220970869120796f
#define SB2   0.0255155128118852f
#define EMB_C 26.6692994f

// ---- device scratch ----
__device__ __half2 g_h0[NE*16];
__device__ __half2 g_h1[NE*16];
__device__ __half2 g_h2[NE*16];
__device__ float g_sh[NE*3];
__device__ __half2 g_P0h[200*640];
__device__ float g_acc0[NN*56];
__device__ float g_acc1[NN*56];
__device__ float g_acc2[NN*16];
// CSR by src
__device__ int g_deg[NN], g_rowptr[NN+1];
__device__ int g_psrc[NE], g_pdst[NE], g_rank[NE];

__device__ __forceinline__ __half2 q0(uint4 v){ return *reinterpret_cast<__half2*>(&v.x); }
__device__ __forceinline__ __half2 q1(uint4 v){ return *reinterpret_cast<__half2*>(&v.y); }
__device__ __forceinline__ __half2 q2(uint4 v){ return *reinterpret_cast<__half2*>(&v.z); }
__device__ __forceinline__ __half2 q3(uint4 v){ return *reinterpret_cast<__half2*>(&v.w); }

// ---- zero deg (blocks 0..31) + P0 build (blocks 32..231), quad-interleaved ----
__global__ void kZeroP0(const float* __restrict__ Ez, const float* __restrict__ Em,
                        const float* __restrict__ W20)
{
    int t = threadIdx.x;
    if (blockIdx.x < 32) {
        int i = blockIdx.x * 256 + t;
        if (i < NN) g_deg[i] = 0;
        return;
    }
    __shared__ float xe[64];
    int c = blockIdx.x - 32;
    int z = c >> 1, mo = c & 1;
    if (t < 48) xe[t] = Ez[z*48 + t];
    else if (t < 64) xe[t] = Em[mo*16 + (t - 48)];
    __syncthreads();
    for (int idx = t; idx < 640; idx += 256) {
        float a0 = 0.f, a1 = 0.f;
        int sidx;
        if (idx < 512) {
            int m2 = idx >> 5, ow = idx & 31;
            const float* W0 = W20 + (2*m2)*2560 + ow;
            const float* W1 = W20 + (2*m2+1)*2560 + ow;
#pragma unroll
            for (int u = 0; u < 64; u++) { a0 += xe[u]*W0[u*32]; a1 += xe[u]*W1[u*32]; }
            sidx = (m2 >> 2)*128 + ow*4 + (m2 & 3);
        } else {
            int r = idx - 512, m2 = r >> 3, ov = r & 7;
            const float* W0 = W20 + (2*m2)*2560 + 2048 + ov;
            const float* W1 = W20 + (2*m2+1)*2560 + 2048 + ov;
#pragma unroll
            for (int u = 0; u < 64; u++) { a0 += xe[u]*W0[u*8]; a1 += xe[u]*W1[u*8]; }
            sidx = 512 + (m2 >> 2)*32 + ov*4 + (m2 & 3);
        }
        g_P0h[c*640 + sidx] = __floats2half2_rn(a0*S0, a1*S0);
    }
}

// ---- degree count + per-edge rank ----
__global__ void kDeg(const int* __restrict__ src)
{
    int e = blockIdx.x * 256 + threadIdx.x;
    if (e < NE) g_rank[e] = atomicAdd(&g_deg[src[e]], 1);
}

__global__ void kScan()
{
    __shared__ int s[1024];
    int t = threadIdx.x;
    int v[8]; int sum = 0;
#pragma unroll
    for (int k = 0; k < 8; k++) { v[k] = g_deg[t*8 + k]; sum += v[k]; }
    s[t] = sum; __syncthreads();
    for (int off = 1; off < 1024; off <<= 1) {
        int x = (t >= off) ? s[t - off] : 0;
        __syncthreads();
        s[t] += x;
        __syncthreads();
    }
    int excl = (t > 0) ? s[t-1] : 0;
#pragma unroll
    for (int k = 0; k < 8; k++) { g_rowptr[t*8 + k] = excl; excl += v[k]; }
    if (t == 1023) g_rowptr[NN] = excl;
}

// ---- edge geometry/radial/hidden (CSR order, packed fp16) + scatter + zeroing ----
__global__ void kHP(const float* __restrict__ pos, const int* __restrict__ src,
                    const int* __restrict__ dst, const float* __restrict__ W10,
                    const float* __restrict__ W11, const float* __restrict__ W12)
{
    __shared__ float semb[8][10];
    int t = threadIdx.x;
    int gid = blockIdx.x * 256 + t;
    if (gid < NN*56) { g_acc0[gid] = 0.f; g_acc1[gid] = 0.f; }
    if (gid < NN*16) g_acc2[gid] = 0.f;

    int warp = t >> 5, lane = t & 31;
    int e = blockIdx.x * 8 + warp;
    int s = src[e], d = dst[e];
    int p = g_rowptr[s] + g_rank[e];
    float vx = pos[d*3+0] - pos[s*3+0];
    float vy = pos[d*3+1] - pos[s*3+1];
    float vz = pos[d*3+2] - pos[s*3+2];
    float len = sqrtf(vx*vx + vy*vy + vz*vz);
    float inv = 1.f / fmaxf(len, 1e-9f);
    if (lane == 0) {
        g_psrc[p] = s; g_pdst[p] = d;
        g_sh[p*3+0] = 1.7320508075688772f * vx * inv;
        g_sh[p*3+1] = 1.7320508075688772f * vy * inv;
        g_sh[p*3+2] = 1.7320508075688772f * vz * inv;
    }
    if (lane < 10) {
        float val = (10.0f * (float)(lane + 1)) / 11.0f;
        float u = (len - val) * 1.1f;
        float em = 0.f;
        if (u > -1.f && u < 1.f)
            em = EMB_C * __expf(-1.f/(1.f+u) - 1.f/(1.f-u));
        semb[warp][lane] = em;
    }
    __syncwarp();
    float emb[10];
#pragma unroll
    for (int j = 0; j < 10; j++) emb[j] = semb[warp][j];
    float a0 = 0.f, a1 = 0.f, a2 = 0.f;
#pragma unroll
    for (int k = 0; k < 10; k++) {
        a0 += emb[k] * W10[k*32 + lane];
        a1 += emb[k] * W11[k*32 + lane];
        a2 += emb[k] * W12[k*32 + lane];
    }
    a0 *= INV_SQRT10; a1 *= INV_SQRT10; a2 *= INV_SQRT10;
    float h0 = a0 / (1.f + __expf(-a0));
    float h1 = a1 / (1.f + __expf(-a1));
    float h2 = a2 / (1.f + __expf(-a2));
    int pl = (lane & 15) * 2;
    float h0lo = __shfl_sync(0xffffffffu, h0, pl),  h0hi = __shfl_sync(0xffffffffu, h0, pl+1);
    float h1lo = __shfl_sync(0xffffffffu, h1, pl),  h1hi = __shfl_sync(0xffffffffu, h1, pl+1);
    float h2lo = __shfl_sync(0xffffffffu, h2, pl),  h2hi = __shfl_sync(0xffffffffu, h2, pl+1);
    if (lane < 16) {
        g_h0[p*16 + lane] = __floats2half2_rn(h0lo, h0hi);
        g_h1[p*16 + lane] = __floats2half2_rn(h1lo, h1hi);
        g_h2[p*16 + lane] = __floats2half2_rn(h2lo, h2hi);
    }
}

// ---- block0 edge kernel (quad-interleaved fp16 tables + LDS.128) ----
__global__ void __launch_bounds__(256) kE0n(const int* __restrict__ z,
                                            const int* __restrict__ mol)
{
    __shared__ __half2 smh[8*640];
    __shared__ int sc[8];
    int t = threadIdx.x, warp = t >> 5, lane = t & 31;
    int nb = blockIdx.x * 8;
    if (t < 8) sc[t] = z[nb + t]*2 + mol[nb + t];
    __syncthreads();
    for (int idx = t; idx < 8*640; idx += 256) {
        int nn = idx / 640, r = idx - nn*640;
        smh[idx] = g_P0h[sc[nn]*640 + r];
    }
    __syncthreads();
    int r0 = g_rowptr[nb], r1 = g_rowptr[nb + 8];
    int iidx = lane >> 3, ov = lane & 7;
    const __half2 z2 = __float2half2_rn(0.f);
    for (int j = r0 + warp; j < r1; j += 8) {
        int s = g_psrc[j], d = g_pdst[j];
        const __half2* T = smh + (s - nb)*640;
        __half2 hl2 = g_h0[j*16 + (lane & 15)];
        __half2 es2 = z2, vC2 = z2;
        float es = 0.f, vC = 0.f;
#pragma unroll
        for (int kq = 0; kq < 4; kq++) {
            __half2 hm0 = __shfl_sync(0xffffffffu, hl2, 4*kq);
            __half2 hm1 = __shfl_sync(0xffffffffu, hl2, 4*kq+1);
            __half2 hm2 = __shfl_sync(0xffffffffu, hl2, 4*kq+2);
            __half2 hm3 = __shfl_sync(0xffffffffu, hl2, 4*kq+3);
            uint4 va = *reinterpret_cast<const uint4*>(T + kq*128 + lane*4);
            uint4 vc = *reinterpret_cast<const uint4*>(T + 512 + kq*32 + ov*4);
            es2 = __hfma2(hm0, q0(va), es2); es2 = __hfma2(hm1, q1(va), es2);
            es2 = __hfma2(hm2, q2(va), es2); es2 = __hfma2(hm3, q3(va), es2);
            vC2 = __hfma2(hm0, q0(vc), vC2); vC2 = __hfma2(hm1, q1(vc), vC2);
            vC2 = __hfma2(hm2, q2(vc), vC2); vC2 = __hfma2(hm3, q3(vc), vC2);
            if (kq == 1 || kq == 3) {
                float2 f = __half22float2(es2); es += f.x + f.y; es2 = z2;
                f = __half22float2(vC2); vC += f.x + f.y; vC2 = z2;
            }
        }
        atomicAdd(&g_acc0[d*56 + lane], es);
        if (lane < 24) {
            float shi = g_sh[j*3 + iidx];
            atomicAdd(&g_acc0[d*56 + 32 + ov*3 + iidx], vC * shi);
        }
    }
}

// ---- per-node LN into smem xs/xv (one warp per node) ----
__device__ __forceinline__ void ln_node(const float* __restrict__ acc, int n, int lane,
                                        const float* __restrict__ g, const float* __restrict__ b,
                                        float* xs_row, float* xv_row)
{
    float v0 = acc[n*56 + lane] * INV_SQRT8;
    float v1 = (lane < 24) ? acc[n*56 + 32 + lane] * INV_SQRT8 : 0.f;
    float sum = v0 + v1;
#pragma unroll
    for (int o = 16; o; o >>= 1) sum += __shfl_xor_sync(0xffffffffu, sum, o);
    float mean = sum * (1.f/56.f);
    float d0 = v0 - mean;
    float d1 = (lane < 24) ? v1 - mean : 0.f;
    float sq = d0*d0 + d1*d1;
#pragma unroll
    for (int o = 16; o; o >>= 1) sq += __shfl_xor_sync(0xffffffffu, sq, o);
    float rstd = rsqrtf(sq * (1.f/56.f) + 1e-5f);
    xs_row[lane] = d0 * rstd * g[lane] + b[lane];
    if (lane < 24)
        xv_row[lane] = d1 * rstd * g[32 + lane] + b[32 + lane];
}

// ---- FUSED block1: LN(acc0) -> build quad-interleaved fp16 T1 for 16 nodes -> edges ----
// half2 layout per node (2944 h2):
//   A @0:    (m2>>2)*128 + ow*4 + (m2&3)
//   B @512:  i*512 + (m2>>2)*128 + ow*4 + (m2&3)
//   C @2048: (m2>>2)*32 + ov*4 + (m2&3)
//   D @2176: i*128 + (m2>>2)*32 + ov*4 + (m2&3)
//   Dv@2560: i*128 + (m2>>2)*32 + ov*4 + (m2&3)
// 16 nodes/block: halves per-block W2 L2 traffic. 188416 B smem, 1 block/SM.
__global__ void __launch_bounds__(512) kE1f(const float* __restrict__ W2,
                                            const float* __restrict__ lng,
                                            const float* __restrict__ lnb)
{
    extern __shared__ __half2 smh[];     // 16 * 2944 half2 = 188416 B
    __shared__ float xs[16][32];
    __shared__ float xv[16][24];
    int t = threadIdx.x, warp = t >> 5, lane = t & 31;
    int nb = blockIdx.x * 16;
    ln_node(g_acc0, nb + warp, lane, lng, lnb, xs[warp], xv[warp]);
    __syncthreads();
    // A (512 entries: m2<16, ow<32)
    {
        int m2 = t >> 5, ow = t & 31;
        const float* W0 = W2 + (2*m2)*1664 + ow;
        const float* W1 = W2 + (2*m2+1)*1664 + ow;
        float a0[16], a1[16];
#pragma unroll
        for (int nn = 0; nn < 16; nn++) { a0[nn] = 0.f; a1[nn] = 0.f; }
#pragma unroll
        for (int u = 0; u < 32; u++) {
            float w0 = W0[u*32], w1 = W1[u*32];
#pragma unroll
            for (int nn = 0; nn < 16; nn++) {
                a0[nn] += xs[nn][u] * w0;
                a1[nn] += xs[nn][u] * w1;
            }
        }
        int sidx = (m2 >> 2)*128 + ow*4 + (m2 & 3);
#pragma unroll
        for (int nn = 0; nn < 16; nn++)
            smh[nn*2944 + sidx] = __floats2half2_rn(a0[nn]*SA1, a1[nn]*SA1);
    }
    // B (1536 entries: i<3, m2<16, ow<32)
    for (int idx = t; idx < 1536; idx += 512) {
        int i = idx >> 9, r = idx & 511, m2 = r >> 5, ow = r & 31;
        const float* W0 = W2 + (2*m2)*1664 + 1024 + ow;
        const float* W1 = W2 + (2*m2+1)*1664 + 1024 + ow;
        float a0[16], a1[16];
#pragma unroll
        for (int nn = 0; nn < 16; nn++) { a0[nn] = 0.f; a1[nn] = 0.f; }
#pragma unroll
        for (int u = 0; u < 8; u++) {
            float w0 = W0[u*32], w1 = W1[u*32];
#pragma unroll
            for (int nn = 0; nn < 16; nn++) {
                a0[nn] += xv[nn][u*3 + i] * w0;
                a1[nn] += xv[nn][u*3 + i] * w1;
            }
        }
        int sidx = 512 + i*512 + (m2 >> 2)*128 + ow*4 + (m2 & 3);
#pragma unroll
        for (int nn = 0; nn < 16; nn++)
            smh[nn*2944 + sidx] = __floats2half2_rn(a0[nn]*SB1, a1[nn]*SB1);
    }
    // C (128 entries: m2<16, ov<8)
    if (t < 128) {
        int m2 = t >> 3, ov = t & 7;
        const float* W0 = W2 + (2*m2)*1664 + 1280 + ov;
        const float* W1 = W2 + (2*m2+1)*1664 + 1280 + ov;
        float a0[16], a1[16];
#pragma unroll
        for (int nn = 0; nn < 16; nn++) { a0[nn] = 0.f; a1[nn] = 0.f; }
#pragma unroll
        for (int u = 0; u < 32; u++) {
            float w0 = W0[u*8], w1 = W1[u*8];
#pragma unroll
            for (int nn = 0; nn < 16; nn++) {
                a0[nn] += xs[nn][u] * w0;
                a1[nn] += xs[nn][u] * w1;
            }
        }
        int sidx = 2048 + (m2 >> 2)*32 + ov*4 + (m2 & 3);
#pragma unroll
        for (int nn = 0; nn < 16; nn++)
            smh[nn*2944 + sidx] = __floats2half2_rn(a0[nn]*SC1, a1[nn]*SC1);
    }
    // D (384: i<3, m2<16, ov<8)
    if (t < 384) {
        int i = t >> 7, r = t & 127, m2 = r >> 3, ov = r & 7;
        const float* W0 = W2 + (2*m2)*1664 + 1536 + ov;
        const float* W1 = W2 + (2*m2+1)*1664 + 1536 + ov;
        float a0[16], a1[16];
#pragma unroll
        for (int nn = 0; nn < 16; nn++) { a0[nn] = 0.f; a1[nn] = 0.f; }
#pragma unroll
        for (int u = 0; u < 8; u++) {
            float w0 = W0[u*8], w1 = W1[u*8];
#pragma unroll
            for (int nn = 0; nn < 16; nn++) {
                a0[nn] += xv[nn][u*3 + i] * w0;
                a1[nn] += xv[nn][u*3 + i] * w1;
            }
        }
        int sidx = 2176 + i*128 + (m2 >> 2)*32 + ov*4 + (m2 & 3);
#pragma unroll
        for (int nn = 0; nn < 16; nn++)
            smh[nn*2944 + sidx] = __floats2half2_rn(a0[nn]*SD1, a1[nn]*SD1);
    }
    // Dv (384)
    if (t < 384) {
        int i = t >> 7, r = t & 127, m2 = r >> 3, ov = r & 7;
        const float* W0 = W2 + (2*m2)*1664 + 1600 + ov;
        const float* W1 = W2 + (2*m2+1)*1664 + 1600 + ov;
        float a0[16], a1[16];
#pragma unroll
        for (int nn = 0; nn < 16; nn++) { a0[nn] = 0.f; a1[nn] = 0.f; }
#pragma unroll
        for (int u = 0; u < 8; u++) {
            float w0 = W0[u*8], w1 = W1[u*8];
#pragma unroll
            for (int nn = 0; nn < 16; nn++) {
                a0[nn] += xv[nn][u*3 + i] * w0;
                a1[nn] += xv[nn][u*3 + i] * w1;
            }
        }
        int sidx = 2560 + i*128 + (m2 >> 2)*32 + ov*4 + (m2 & 3);
#pragma unroll
        for (int nn = 0; nn < 16; nn++)
            smh[nn*2944 + sidx] = __floats2half2_rn(a0[nn]*SDV1, a1[nn]*SDV1);
    }
    __syncthreads();

    // edge phase: 16 warps, warp-strided; LDS.128 quad loads, HFMA2, flush at kq=1,3.
    int r0 = g_rowptr[nb], r1 = g_rowptr[nb + 16];
    int iidx = lane >> 3, ov = lane & 7;
    int ovc = lane - 24;
    int j1 = (iidx == 0) ? 1 : ((iidx == 1) ? 2 : 0);
    int j2 = (iidx == 0) ? 2 : ((iidx == 1) ? 0 : 1);
    int off5 = (lane < 24) ? (2176 + iidx*128 + ov*4) : (2048 + ovc*4);
    int off6 = (lane < 24) ? (2560 + iidx*128 + ov*4) : (ov*4);
    const __half2 z2 = __float2half2_rn(0.f);
    for (int j = r0 + warp; j < r1; j += 16) {
        int s = g_psrc[j], d = g_pdst[j];
        const __half2* T = smh + (s - nb)*2944;
        __half2 hl2 = g_h1[j*16 + (lane & 15)];
        float sh0 = g_sh[j*3+0], sh1 = g_sh[j*3+1], sh2 = g_sh[j*3+2];
        __half2 es2 = z2, e02 = z2, e12 = z2, e22 = z2, a52 = z2, a62 = z2;
        float es = 0.f, e0 = 0.f, e1 = 0.f, e2 = 0.f, a5 = 0.f, a6 = 0.f;
#pragma unroll
        for (int kq = 0; kq < 4; kq++) {
            __half2 hm0 = __shfl_sync(0xffffffffu, hl2, 4*kq);
            __half2 hm1 = __shfl_sync(0xffffffffu, hl2, 4*kq+1);
            __half2 hm2 = __shfl_sync(0xffffffffu, hl2, 4*kq+2);
            __half2 hm3 = __shfl_sync(0xffffffffu, hl2, 4*kq+3);
            uint4 va  = *reinterpret_cast<const uint4*>(T + kq*128 + lane*4);
            uint4 vb0 = *reinterpret_cast<const uint4*>(T + 512  + kq*128 + lane*4);
            uint4 vb1 = *reinterpret_cast<const uint4*>(T + 1024 + kq*128 + lane*4);
            uint4 vb2 = *reinterpret_cast<const uint4*>(T + 1536 + kq*128 + lane*4);
            uint4 v5  = *reinterpret_cast<const uint4*>(T + off5 + kq*32);
            uint4 v6  = *reinterpret_cast<const uint4*>(T + off6 + kq*32);
            es2 = __hfma2(hm0, q0(va),  es2); es2 = __hfma2(hm1, q1(va),  es2);
            es2 = __hfma2(hm2, q2(va),  es2); es2 = __hfma2(hm3, q3(va),  es2);
            e02 = __hfma2(hm0, q0(vb0), e02); e02 = __hfma2(hm1, q1(vb0), e02);
            e02 = __hfma2(hm2, q2(vb0), e02); e02 = __hfma2(hm3, q3(vb0), e02);
            e12 = __hfma2(hm0, q0(vb1), e12); e12 = __hfma2(hm1, q1(vb1), e12);
            e12 = __hfma2(hm2, q2(vb1), e12); e12 = __hfma2(hm3, q3(vb1), e12);
            e22 = __hfma2(hm0, q0(vb2), e22); e22 = __hfma2(hm1, q1(vb2), e22);
            e22 = __hfma2(hm2, q2(vb2), e22); e22 = __hfma2(hm3, q3(vb2), e22);
            a52 = __hfma2(hm0, q0(v5),  a52); a52 = __hfma2(hm1, q1(v5),  a52);
            a52 = __hfma2(hm2, q2(v5),  a52); a52 = __hfma2(hm3, q3(v5),  a52);
            a62 = __hfma2(hm0, q0(v6),  a62); a62 = __hfma2(hm1, q1(v6),  a62);
            a62 = __hfma2(hm2, q2(v6),  a62); a62 = __hfma2(hm3, q3(v6),  a62);
            if (kq == 1 || kq == 3) {
                float2 f;
                f = __half22float2(es2); es += f.x + f.y; es2 = z2;
                f = __half22float2(e02); e0 += f.x + f.y; e02 = z2;
                f = __half22float2(e12); e1 += f.x + f.y; e12 = z2;
                f = __half22float2(e22); e2 += f.x + f.y; e22 = z2;
                f = __half22float2(a52); a5 += f.x + f.y; a52 = z2;
                f = __half22float2(a62); a6 += f.x + f.y; a62 = z2;
            }
        }
        es += sh0*e0 + sh1*e1 + sh2*e2;
        atomicAdd(&g_acc1[d*56 + lane], es);
        float C_ov  = __shfl_sync(0xffffffffu, a5, 24 + ov);
        float Dv_j1 = __shfl_sync(0xffffffffu, a6, j1*8 + ov);
        float Dv_j2 = __shfl_sync(0xffffffffu, a6, j2*8 + ov);
        if (lane < 24) {
            float shi  = (iidx == 0) ? sh0 : ((iidx == 1) ? sh1 : sh2);
            float shj1 = (j1 == 0) ? sh0 : ((j1 == 1) ? sh1 : sh2);
            float shj2 = (j2 == 0) ? sh0 : ((j2 == 1) ? sh1 : sh2);
            float ev = shi*C_ov + a5 + shj2*Dv_j1 - shj1*Dv_j2;
            atomicAdd(&g_acc1[d*56 + 32 + ov*3 + iidx], ev);
        }
    }
}

// ---- FUSED block2: LN(acc1) -> quad-interleaved fp16 tables -> LDS.128 edges ----
__global__ void __launch_bounds__(256) kE2f(const float* __restrict__ W2,
                                            const float* __restrict__ lng,
                                            const float* __restrict__ lnb)
{
    extern __shared__ __half2 smh[];   // 8 * 1024 half2 = 32768 B
    __shared__ float xs[8][32];
    __shared__ float xv[8][24];
    int t = threadIdx.x, warp = t >> 5, lane = t & 31;
    int nb = blockIdx.x * 8;
    ln_node(g_acc1, nb + warp, lane, lng, lnb, xs[warp], xv[warp]);
    __syncthreads();
    if (t < 256) {
        int m2 = t >> 4, ow = t & 15;
        const float* W0 = W2 + (2*m2)*640 + ow;
        const float* W1 = W2 + (2*m2+1)*640 + ow;
        float a0[8] = {0,0,0,0,0,0,0,0}, a1[8] = {0,0,0,0,0,0,0,0};
#pragma unroll
        for (int u = 0; u < 32; u++) {
            float w0 = W0[u*16], w1 = W1[u*16];
#pragma unroll
            for (int nn = 0; nn < 8; nn++) {
                a0[nn] += xs[nn][u] * w0;
                a1[nn] += xs[nn][u] * w1;
            }
        }
        int sidx = (m2 >> 2)*64 + ow*4 + (m2 & 3);
#pragma unroll
        for (int nn = 0; nn < 8; nn++)
            smh[nn*1024 + sidx] = __floats2half2_rn(a0[nn]*SA2, a1[nn]*SA2);
    }
    for (int idx = t; idx < 768; idx += 256) {
        int i = idx >> 8, r = idx & 255, m2 = r >> 4, ow = r & 15;
        const float* W0 = W2 + (2*m2)*640 + 512 + ow;
        const float* W1 = W2 + (2*m2+1)*640 + 512 + ow;
        float a0[8] = {0,0,0,0,0,0,0,0}, a1[8] = {0,0,0,0,0,0,0,0};
#pragma unroll
        for (int u = 0; u < 8; u++) {
            float w0 = W0[u*16], w1 = W1[u*16];
#pragma unroll
            for (int nn = 0; nn < 8; nn++) {
                a0[nn] += xv[nn][u*3 + i] * w0;
                a1[nn] += xv[nn][u*3 + i] * w1;
            }
        }
        int sidx = 256 + i*256 + (m2 >> 2)*64 + ow*4 + (m2 & 3);
#pragma unroll
        for (int nn = 0; nn < 8; nn++)
            smh[nn*1024 + sidx] = __floats2half2_rn(a0[nn]*SB2, a1[nn]*SB2);
    }
    __syncthreads();

    int r0 = g_rowptr[nb], r1 = g_rowptr[nb + 8];
    int sub = lane >> 4, ow = lane & 15;
    unsigned hmask = sub ? 0xffff0000u : 0x0000ffffu;
    const __half2 z2 = __float2half2_rn(0.f);
    for (int j = r0 + warp*2 + sub; j < r1; j += 16) {
        int s = g_psrc[j], d = g_pdst[j];
        const __half2* T = smh + (s - nb)*1024;
        __half2 hl2 = g_h2[j*16 + ow];
        float sh0 = g_sh[j*3+0], sh1 = g_sh[j*3+1], sh2 = g_sh[j*3+2];
        __half2 es2 = z2, e02 = z2, e12 = z2, e22 = z2;
        float es = 0.f, e0 = 0.f, e1 = 0.f, e2 = 0.f;
#pragma unroll
        for (int kq = 0; kq < 4; kq++) {
            __half2 hm0 = __shfl_sync(hmask, hl2, (sub << 4) + 4*kq);
            __half2 hm1 = __shfl_sync(hmask, hl2, (sub << 4) + 4*kq+1);
            __half2 hm2 = __shfl_sync(hmask, hl2, (sub << 4) + 4*kq+2);
            __half2 hm3 = __shfl_sync(hmask, hl2, (sub << 4) + 4*kq+3);
            uint4 va  = *reinterpret_cast<const uint4*>(T + kq*64 + ow*4);
            uint4 vb0 = *reinterpret_cast<const uint4*>(T + 256 + kq*64 + ow*4);
            uint4 vb1 = *reinterpret_cast<const uint4*>(T + 512 + kq*64 + ow*4);
            uint4 vb2 = *reinterpret_cast<const uint4*>(T + 768 + kq*64 + ow*4);
            es2 = __hfma2(hm0, q0(va),  es2); es2 = __hfma2(hm1, q1(va),  es2);
            es2 = __hfma2(hm2, q2(va),  es2); es2 = __hfma2(hm3, q3(va),  es2);
            e02 = __hfma2(hm0, q0(vb0), e02); e02 = __hfma2(hm1, q1(vb0), e02);
            e02 = __hfma2(hm2, q2(vb0), e02); e02 = __hfma2(hm3, q3(vb0), e02);
            e12 = __hfma2(hm0, q0(vb1), e12); e12 = __hfma2(hm1, q1(vb1), e12);
            e12 = __hfma2(hm2, q2(vb1), e12); e12 = __hfma2(hm3, q3(vb1), e12);
            e22 = __hfma2(hm0, q0(vb2), e22); e22 = __hfma2(hm1, q1(vb2), e22);
            e22 = __hfma2(hm2, q2(vb2), e22); e22 = __hfma2(hm3, q3(vb2), e22);
            if (kq == 1 || kq == 3) {
                float2 f;
                f = __half22float2(es2); es += f.x + f.y; es2 = z2;
                f = __half22float2(e02); e0 += f.x + f.y; e02 = z2;
                f = __half22float2(e12); e1 += f.x + f.y; e12 = z2;
                f = __half22float2(e22); e2 += f.x + f.y; e22 = z2;
            }
        }
        es += sh0*e0 + sh1*e1 + sh2*e2;
        atomicAdd(&g_acc2[d*16 + ow], es);
    }
}

// ---- final layernorm over 16 dims -> d_out ----
__global__ void kLN16(const float* __restrict__ g, const float* __restrict__ b,
                      float* __restrict__ out)
{
    int warp = threadIdx.x >> 5, lane = threadIdx.x & 31;
    int n = blockIdx.x * 8 + warp;
    float v = (lane < 16) ? g_acc2[n*16 + lane] * INV_SQRT8 : 0.f;
    float sum = v;
#pragma unroll
    for (int o = 16; o; o >>= 1) sum += __shfl_xor_sync(0xffffffffu, sum, o);
    float mean = sum * (1.f/16.f);
    float dd = (lane < 16) ? v - mean : 0.f;
    float sq = dd*dd;
#pragma unroll
    for (int o = 16; o; o >>= 1) sq += __shfl_xor_sync(0xffffffffu, sq, o);
    float rstd = rsqrtf(sq * (1.f/16.f) + 1e-5f);
    if (lane < 16) out[n*16 + lane] = dd * rstd * g[lane] + b[lane];
}

extern "C" void kernel_launch(void* const* d_in, const int* in_sizes, int n_in,
                              void* d_out, int out_size)
{
    (void)in_sizes; (void)n_in; (void)out_size;
    const float* pos  = (const float*)d_in[0];
    const int*   z    = (const int*)d_in[1];
    const int*   mol  = (const int*)d_in[2];
    const int*   src  = (const int*)d_in[3];
    const int*   dst  = (const int*)d_in[4];
    const float* Ez   = (const float*)d_in[5];
    const float* Em   = (const float*)d_in[6];
    const float* b0W1 = (const float*)d_in[7];
    const float* b0W2 = (const float*)d_in[8];
    const float* b0g  = (const float*)d_in[9];
    const float* b0b  = (const float*)d_in[10];
    const float* b1W1 = (const float*)d_in[11];
    const float* b1W2 = (const float*)d_in[12];
    const float* b1g  = (const float*)d_in[13];
    const float* b1b  = (const float*)d_in[14];
    const float* b2W1 = (const float*)d_in[15];
    const float* b2W2 = (const float*)d_in[16];
    const float* b2g  = (const float*)d_in[17];
    const float* b2b  = (const float*)d_in[18];
    float* out = (float*)d_out;

    static int attr_done = 0;
    if (!attr_done) {
        cudaFuncSetAttribute(kE1f, cudaFuncAttributeMaxDynamicSharedMemorySize, 16*2944*4);
        cudaFuncSetAttribute(kE2f, cudaFuncAttributeMaxDynamicSharedMemorySize, 8*1024*4);
        attr_done = 1;
    }

    kZeroP0  <<<232, 256>>>(Ez, Em, b0W2);
    kDeg     <<<NE/256, 256>>>(src);
    kScan    <<<1, 1024>>>();
    kHP      <<<NE/8, 256>>>(pos, src, dst, b0W1, b1W1, b2W1);
    kE0n     <<<NN/8, 256>>>(z, mol);
    kE1f     <<<NN/16, 512, 16*2944*4>>>(b1W2, b0g, b0b);
    kE2f     <<<NN/8, 256, 8*1024*4>>>(b2W2, b1g, b1b);
    kLN16    <<<NN/8, 256>>>(b2g, b2b, out);
}

// round 16
// speedup vs baseline: 1.9030x; 1.9030x over previous
#include <cuda_runtime.h>
#include <cuda_fp16.h>
#include <math.h>

#define NN 8192
#define NE 65536

// ---- folded normalization constants ----
#define INV_SQRT10 0.3162277660168379f
#define INV_SQRT8  0.3535533905932738f
#define S0    0.0220970869120796f
#define SA1   0.0220970869120796f
#define SB1   0.0255155128118852f
#define SC1   0.0180421959121758f
#define SD1   0.0360843918243516f
#define SDV1  0.0255155128118852f
#define SA2   0.0220970869120796f
#define SB2   0.0255155128118852f
#define EMB_C 26.6692994f

// ---- device scratch ----
__device__ __half2 g_h0[NE*16];   // h packed as pairs: [e][l] = (h[2l], h[2l+1])
__device__ __half2 g_h1[NE*16];
__device__ __half2 g_h2[NE*16];
__device__ float g_sh[NE*3];
__device__ __half2 g_P0h[200*640];
__device__ float g_acc0[NN*56];
__device__ float g_acc1[NN*56];
__device__ float g_acc2[NN*16];
// CSR by src
__device__ int g_deg[NN], g_rowptr[NN+1];
__device__ int g_psrc[NE], g_pdst[NE], g_rank[NE];

__device__ __forceinline__ __half2 q0(uint4 v){ return *reinterpret_cast<__half2*>(&v.x); }
__device__ __forceinline__ __half2 q1(uint4 v){ return *reinterpret_cast<__half2*>(&v.y); }
__device__ __forceinline__ __half2 q2(uint4 v){ return *reinterpret_cast<__half2*>(&v.z); }
__device__ __forceinline__ __half2 q3(uint4 v){ return *reinterpret_cast<__half2*>(&v.w); }

// ---- zero deg (blocks 0..31) + P0 build (blocks 32..231), quad-interleaved ----
// scalar: (m2,ow) -> (m2>>2)*128 + ow*4 + (m2&3)   (512 h2)
// vec:    512 + (m2>>2)*32 + ov*4 + (m2&3)         (128 h2)
__global__ void kZeroP0(const float* __restrict__ Ez, const float* __restrict__ Em,
                        const float* __restrict__ W20)
{
    int t = threadIdx.x;
    if (blockIdx.x < 32) {
        int i = blockIdx.x * 256 + t;
        if (i < NN) g_deg[i] = 0;
        return;
    }
    __shared__ float xe[64];
    int c = blockIdx.x - 32;
    int z = c >> 1, mo = c & 1;
    if (t < 48) xe[t] = Ez[z*48 + t];
    else if (t < 64) xe[t] = Em[mo*16 + (t - 48)];
    __syncthreads();
    for (int idx = t; idx < 640; idx += 256) {
        float a0 = 0.f, a1 = 0.f;
        int sidx;
        if (idx < 512) {
            int m2 = idx >> 5, ow = idx & 31;
            const float* W0 = W20 + (2*m2)*2560 + ow;
            const float* W1 = W20 + (2*m2+1)*2560 + ow;
#pragma unroll
            for (int u = 0; u < 64; u++) { a0 += xe[u]*W0[u*32]; a1 += xe[u]*W1[u*32]; }
            sidx = (m2 >> 2)*128 + ow*4 + (m2 & 3);
        } else {
            int r = idx - 512, m2 = r >> 3, ov = r & 7;
            const float* W0 = W20 + (2*m2)*2560 + 2048 + ov;
            const float* W1 = W20 + (2*m2+1)*2560 + 2048 + ov;
#pragma unroll
            for (int u = 0; u < 64; u++) { a0 += xe[u]*W0[u*8]; a1 += xe[u]*W1[u*8]; }
            sidx = 512 + (m2 >> 2)*32 + ov*4 + (m2 & 3);
        }
        g_P0h[c*640 + sidx] = __floats2half2_rn(a0*S0, a1*S0);
    }
}

// ---- degree count + per-edge rank ----
__global__ void kDeg(const int* __restrict__ src)
{
    int e = blockIdx.x * 256 + threadIdx.x;
    if (e < NE) g_rank[e] = atomicAdd(&g_deg[src[e]], 1);
}

__global__ void kScan()
{
    __shared__ int s[1024];
    int t = threadIdx.x;
    int v[8]; int sum = 0;
#pragma unroll
    for (int k = 0; k < 8; k++) { v[k] = g_deg[t*8 + k]; sum += v[k]; }
    s[t] = sum; __syncthreads();
    for (int off = 1; off < 1024; off <<= 1) {
        int x = (t >= off) ? s[t - off] : 0;
        __syncthreads();
        s[t] += x;
        __syncthreads();
    }
    int excl = (t > 0) ? s[t-1] : 0;
#pragma unroll
    for (int k = 0; k < 8; k++) { g_rowptr[t*8 + k] = excl; excl += v[k]; }
    if (t == 1023) g_rowptr[NN] = excl;
}

// ---- edge geometry/radial/hidden (CSR order, packed fp16) + scatter + zeroing ----
__global__ void kHP(const float* __restrict__ pos, const int* __restrict__ src,
                    const int* __restrict__ dst, const float* __restrict__ W10,
                    const float* __restrict__ W11, const float* __restrict__ W12)
{
    __shared__ float semb[8][10];
    int t = threadIdx.x;
    int gid = blockIdx.x * 256 + t;
    if (gid < NN*56) { g_acc0[gid] = 0.f; g_acc1[gid] = 0.f; }
    if (gid < NN*16) g_acc2[gid] = 0.f;

    int warp = t >> 5, lane = t & 31;
    int e = blockIdx.x * 8 + warp;
    int s = src[e], d = dst[e];
    int p = g_rowptr[s] + g_rank[e];
    float vx = pos[d*3+0] - pos[s*3+0];
    float vy = pos[d*3+1] - pos[s*3+1];
    float vz = pos[d*3+2] - pos[s*3+2];
    float len = sqrtf(vx*vx + vy*vy + vz*vz);
    float inv = 1.f / fmaxf(len, 1e-9f);
    if (lane == 0) {
        g_psrc[p] = s; g_pdst[p] = d;
        g_sh[p*3+0] = 1.7320508075688772f * vx * inv;
        g_sh[p*3+1] = 1.7320508075688772f * vy * inv;
        g_sh[p*3+2] = 1.7320508075688772f * vz * inv;
    }
    if (lane < 10) {
        float val = (10.0f * (float)(lane + 1)) / 11.0f;
        float u = (len - val) * 1.1f;
        float em = 0.f;
        if (u > -1.f && u < 1.f)
            em = EMB_C * __expf(-1.f/(1.f+u) - 1.f/(1.f-u));
        semb[warp][lane] = em;
    }
    __syncwarp();
    float emb[10];
#pragma unroll
    for (int j = 0; j < 10; j++) emb[j] = semb[warp][j];
    float a0 = 0.f, a1 = 0.f, a2 = 0.f;
#pragma unroll
    for (int k = 0; k < 10; k++) {
        a0 += emb[k] * W10[k*32 + lane];
        a1 += emb[k] * W11[k*32 + lane];
        a2 += emb[k] * W12[k*32 + lane];
    }
    a0 *= INV_SQRT10; a1 *= INV_SQRT10; a2 *= INV_SQRT10;
    float h0 = a0 / (1.f + __expf(-a0));
    float h1 = a1 / (1.f + __expf(-a1));
    float h2 = a2 / (1.f + __expf(-a2));
    int pl = (lane & 15) * 2;
    float h0lo = __shfl_sync(0xffffffffu, h0, pl),  h0hi = __shfl_sync(0xffffffffu, h0, pl+1);
    float h1lo = __shfl_sync(0xffffffffu, h1, pl),  h1hi = __shfl_sync(0xffffffffu, h1, pl+1);
    float h2lo = __shfl_sync(0xffffffffu, h2, pl),  h2hi = __shfl_sync(0xffffffffu, h2, pl+1);
    if (lane < 16) {
        g_h0[p*16 + lane] = __floats2half2_rn(h0lo, h0hi);
        g_h1[p*16 + lane] = __floats2half2_rn(h1lo, h1hi);
        g_h2[p*16 + lane] = __floats2half2_rn(h2lo, h2hi);
    }
}

// ---- block0 edge kernel (quad-interleaved fp16 tables + LDS.128) ----
__global__ void __launch_bounds__(256) kE0n(const int* __restrict__ z,
                                            const int* __restrict__ mol)
{
    __shared__ __half2 smh[8*640];
    __shared__ int sc[8];
    int t = threadIdx.x, warp = t >> 5, lane = t & 31;
    int nb = blockIdx.x * 8;
    if (t < 8) sc[t] = z[nb + t]*2 + mol[nb + t];
    __syncthreads();
    for (int idx = t; idx < 8*640; idx += 256) {
        int nn = idx / 640, r = idx - nn*640;
        smh[idx] = g_P0h[sc[nn]*640 + r];
    }
    __syncthreads();
    int r0 = g_rowptr[nb], r1 = g_rowptr[nb + 8];
    int iidx = lane >> 3, ov = lane & 7;
    const __half2 z2 = __float2half2_rn(0.f);
    for (int j = r0 + warp; j < r1; j += 8) {
        int s = g_psrc[j], d = g_pdst[j];
        const __half2* T = smh + (s - nb)*640;
        __half2 hl2 = g_h0[j*16 + (lane & 15)];
        __half2 es2 = z2, vC2 = z2;
        float es = 0.f, vC = 0.f;
#pragma unroll
        for (int kq = 0; kq < 4; kq++) {
            __half2 hm0 = __shfl_sync(0xffffffffu, hl2, 4*kq);
            __half2 hm1 = __shfl_sync(0xffffffffu, hl2, 4*kq+1);
            __half2 hm2 = __shfl_sync(0xffffffffu, hl2, 4*kq+2);
            __half2 hm3 = __shfl_sync(0xffffffffu, hl2, 4*kq+3);
            uint4 va = *reinterpret_cast<const uint4*>(T + kq*128 + lane*4);
            uint4 vc = *reinterpret_cast<const uint4*>(T + 512 + kq*32 + ov*4);
            es2 = __hfma2(hm0, q0(va), es2); es2 = __hfma2(hm1, q1(va), es2);
            es2 = __hfma2(hm2, q2(va), es2); es2 = __hfma2(hm3, q3(va), es2);
            vC2 = __hfma2(hm0, q0(vc), vC2); vC2 = __hfma2(hm1, q1(vc), vC2);
            vC2 = __hfma2(hm2, q2(vc), vC2); vC2 = __hfma2(hm3, q3(vc), vC2);
            if (kq == 1 || kq == 3) {
                float2 f = __half22float2(es2); es += f.x + f.y; es2 = z2;
                f = __half22float2(vC2); vC += f.x + f.y; vC2 = z2;
            }
        }
        atomicAdd(&g_acc0[d*56 + lane], es);
        if (lane < 24) {
            float shi = g_sh[j*3 + iidx];
            atomicAdd(&g_acc0[d*56 + 32 + ov*3 + iidx], vC * shi);
        }
    }
}

// ---- per-node LN into smem xs/xv (one warp per node) ----
__device__ __forceinline__ void ln_node(const float* __restrict__ acc, int n, int lane,
                                        const float* __restrict__ g, const float* __restrict__ b,
                                        float* xs_row, float* xv_row)
{
    float v0 = acc[n*56 + lane] * INV_SQRT8;
    float v1 = (lane < 24) ? acc[n*56 + 32 + lane] * INV_SQRT8 : 0.f;
    float sum = v0 + v1;
#pragma unroll
    for (int o = 16; o; o >>= 1) sum += __shfl_xor_sync(0xffffffffu, sum, o);
    float mean = sum * (1.f/56.f);
    float d0 = v0 - mean;
    float d1 = (lane < 24) ? v1 - mean : 0.f;
    float sq = d0*d0 + d1*d1;
#pragma unroll
    for (int o = 16; o; o >>= 1) sq += __shfl_xor_sync(0xffffffffu, sq, o);
    float rstd = rsqrtf(sq * (1.f/56.f) + 1e-5f);
    xs_row[lane] = d0 * rstd * g[lane] + b[lane];
    if (lane < 24)
        xv_row[lane] = d1 * rstd * g[32 + lane] + b[32 + lane];
}

// ---- FUSED block1: LN(acc0) -> build quad-interleaved fp16 T1 -> LDS.128 edges ----
// half2 layout per node (2944 h2):
//   A @0:    (m2>>2)*128 + ow*4 + (m2&3)
//   B @512:  i*512 + (m2>>2)*128 + ow*4 + (m2&3)
//   C @2048: (m2>>2)*32 + ov*4 + (m2&3)
//   D @2176: i*128 + (m2>>2)*32 + ov*4 + (m2&3)
//   Dv@2560: i*128 + (m2>>2)*32 + ov*4 + (m2&3)
__global__ void __launch_bounds__(512) kE1f(const float* __restrict__ W2,
                                            const float* __restrict__ lng,
                                            const float* __restrict__ lnb)
{
    extern __shared__ __half2 smh[];     // 8 * 2944 half2 = 94208 B
    __shared__ float xs[8][32];
    __shared__ float xv[8][24];
    int t = threadIdx.x, warp = t >> 5, lane = t & 31;
    int nb = blockIdx.x * 8;
    if (warp < 8)
        ln_node(g_acc0, nb + warp, lane, lng, lnb, xs[warp], xv[warp]);
    __syncthreads();
    // A (512 entries: m2<16, ow<32)
    {
        int m2 = t >> 5, ow = t & 31;
        const float* W0 = W2 + (2*m2)*1664 + ow;
        const float* W1 = W2 + (2*m2+1)*1664 + ow;
        float a0[8] = {0,0,0,0,0,0,0,0}, a1[8] = {0,0,0,0,0,0,0,0};
#pragma unroll
        for (int u = 0; u < 32; u++) {
            float w0 = W0[u*32], w1 = W1[u*32];
#pragma unroll
            for (int nn = 0; nn < 8; nn++) {
                a0[nn] += xs[nn][u] * w0;
                a1[nn] += xs[nn][u] * w1;
            }
        }
        int sidx = (m2 >> 2)*128 + ow*4 + (m2 & 3);
#pragma unroll
        for (int nn = 0; nn < 8; nn++)
            smh[nn*2944 + sidx] = __floats2half2_rn(a0[nn]*SA1, a1[nn]*SA1);
    }
    // B (1536 entries: i<3, m2<16, ow<32)
    for (int idx = t; idx < 1536; idx += 512) {
        int i = idx >> 9, r = idx & 511, m2 = r >> 5, ow = r & 31;
        const float* W0 = W2 + (2*m2)*1664 + 1024 + ow;
        const float* W1 = W2 + (2*m2+1)*1664 + 1024 + ow;
        float a0[8] = {0,0,0,0,0,0,0,0}, a1[8] = {0,0,0,0,0,0,0,0};
#pragma unroll
        for (int u = 0; u < 8; u++) {
            float w0 = W0[u*32], w1 = W1[u*32];
#pragma unroll
            for (int nn = 0; nn < 8; nn++) {
                a0[nn] += xv[nn][u*3 + i] * w0;
                a1[nn] += xv[nn][u*3 + i] * w1;
            }
        }
        int sidx = 512 + i*512 + (m2 >> 2)*128 + ow*4 + (m2 & 3);
#pragma unroll
        for (int nn = 0; nn < 8; nn++)
            smh[nn*2944 + sidx] = __floats2half2_rn(a0[nn]*SB1, a1[nn]*SB1);
    }
    // C (128 entries: m2<16, ov<8)
    if (t < 128) {
        int m2 = t >> 3, ov = t & 7;
        const float* W0 = W2 + (2*m2)*1664 + 1280 + ov;
        const float* W1 = W2 + (2*m2+1)*1664 + 1280 + ov;
        float a0[8] = {0,0,0,0,0,0,0,0}, a1[8] = {0,0,0,0,0,0,0,0};
#pragma unroll
        for (int u = 0; u < 32; u++) {
            float w0 = W0[u*8], w1 = W1[u*8];
#pragma unroll
            for (int nn = 0; nn < 8; nn++) {
                a0[nn] += xs[nn][u] * w0;
                a1[nn] += xs[nn][u] * w1;
            }
        }
        int sidx = 2048 + (m2 >> 2)*32 + ov*4 + (m2 & 3);
#pragma unroll
        for (int nn = 0; nn < 8; nn++)
            smh[nn*2944 + sidx] = __floats2half2_rn(a0[nn]*SC1, a1[nn]*SC1);
    }
    // D (384: i<3, m2<16, ov<8)
    if (t < 384) {
        int i = t >> 7, r = t & 127, m2 = r >> 3, ov = r & 7;
        const float* W0 = W2 + (2*m2)*1664 + 1536 + ov;
        const float* W1 = W2 + (2*m2+1)*1664 + 1536 + ov;
        float a0[8] = {0,0,0,0,0,0,0,0}, a1[8] = {0,0,0,0,0,0,0,0};
#pragma unroll
        for (int u = 0; u < 8; u++) {
            float w0 = W0[u*8], w1 = W1[u*8];
#pragma unroll
            for (int nn = 0; nn < 8; nn++) {
                a0[nn] += xv[nn][u*3 + i] * w0;
                a1[nn] += xv[nn][u*3 + i] * w1;
            }
        }
        int sidx = 2176 + i*128 + (m2 >> 2)*32 + ov*4 + (m2 & 3);
#pragma unroll
        for (int nn = 0; nn < 8; nn++)
            smh[nn*2944 + sidx] = __floats2half2_rn(a0[nn]*SD1, a1[nn]*SD1);
    }
    // Dv (384)
    if (t < 384) {
        int i = t >> 7, r = t & 127, m2 = r >> 3, ov = r & 7;
        const float* W0 = W2 + (2*m2)*1664 + 1600 + ov;
        const float* W1 = W2 + (2*m2+1)*1664 + 1600 + ov;
        float a0[8] = {0,0,0,0,0,0,0,0}, a1[8] = {0,0,0,0,0,0,0,0};
#pragma unroll
        for (int u = 0; u < 8; u++) {
            float w0 = W0[u*8], w1 = W1[u*8];
#pragma unroll
            for (int nn = 0; nn < 8; nn++) {
                a0[nn] += xv[nn][u*3 + i] * w0;
                a1[nn] += xv[nn][u*3 + i] * w1;
            }
        }
        int sidx = 2560 + i*128 + (m2 >> 2)*32 + ov*4 + (m2 & 3);
#pragma unroll
        for (int nn = 0; nn < 8; nn++)
            smh[nn*2944 + sidx] = __floats2half2_rn(a0[nn]*SDV1, a1[nn]*SDV1);
    }
    __syncthreads();

    // edge phase: 16 warps, warp-strided; LDS.128 quad loads, HFMA2, flush at kq=1,3.
    int r0 = g_rowptr[nb], r1 = g_rowptr[nb + 8];
    int iidx = lane >> 3, ov = lane & 7;
    int ovc = lane - 24;
    int j1 = (iidx == 0) ? 1 : ((iidx == 1) ? 2 : 0);
    int j2 = (iidx == 0) ? 2 : ((iidx == 1) ? 0 : 1);
    int off5 = (lane < 24) ? (2176 + iidx*128 + ov*4) : (2048 + ovc*4);
    int off6 = (lane < 24) ? (2560 + iidx*128 + ov*4) : (ov*4);
    const __half2 z2 = __float2half2_rn(0.f);
    for (int j = r0 + warp; j < r1; j += 16) {
        int s = g_psrc[j], d = g_pdst[j];
        const __half2* T = smh + (s - nb)*2944;
        __half2 hl2 = g_h1[j*16 + (lane & 15)];
        float sh0 = g_sh[j*3+0], sh1 = g_sh[j*3+1], sh2 = g_sh[j*3+2];
        __half2 es2 = z2, e02 = z2, e12 = z2, e22 = z2, a52 = z2, a62 = z2;
        float es = 0.f, e0 = 0.f, e1 = 0.f, e2 = 0.f, a5 = 0.f, a6 = 0.f;
#pragma unroll
        for (int kq = 0; kq < 4; kq++) {
            __half2 hm0 = __shfl_sync(0xffffffffu, hl2, 4*kq);
            __half2 hm1 = __shfl_sync(0xffffffffu, hl2, 4*kq+1);
            __half2 hm2 = __shfl_sync(0xffffffffu, hl2, 4*kq+2);
            __half2 hm3 = __shfl_sync(0xffffffffu, hl2, 4*kq+3);
            uint4 va  = *reinterpret_cast<const uint4*>(T + kq*128 + lane*4);
            uint4 vb0 = *reinterpret_cast<const uint4*>(T + 512  + kq*128 + lane*4);
            uint4 vb1 = *reinterpret_cast<const uint4*>(T + 1024 + kq*128 + lane*4);
            uint4 vb2 = *reinterpret_cast<const uint4*>(T + 1536 + kq*128 + lane*4);
            uint4 v5  = *reinterpret_cast<const uint4*>(T + off5 + kq*32);
            uint4 v6  = *reinterpret_cast<const uint4*>(T + off6 + kq*32);
            es2 = __hfma2(hm0, q0(va),  es2); es2 = __hfma2(hm1, q1(va),  es2);
            es2 = __hfma2(hm2, q2(va),  es2); es2 = __hfma2(hm3, q3(va),  es2);
            e02 = __hfma2(hm0, q0(vb0), e02); e02 = __hfma2(hm1, q1(vb0), e02);
            e02 = __hfma2(hm2, q2(vb0), e02); e02 = __hfma2(hm3, q3(vb0), e02);
            e12 = __hfma2(hm0, q0(vb1), e12); e12 = __hfma2(hm1, q1(vb1), e12);
            e12 = __hfma2(hm2, q2(vb1), e12); e12 = __hfma2(hm3, q3(vb1), e12);
            e22 = __hfma2(hm0, q0(vb2), e22); e22 = __hfma2(hm1, q1(vb2), e22);
            e22 = __hfma2(hm2, q2(vb2), e22); e22 = __hfma2(hm3, q3(vb2), e22);
            a52 = __hfma2(hm0, q0(v5),  a52); a52 = __hfma2(hm1, q1(v5),  a52);
            a52 = __hfma2(hm2, q2(v5),  a52); a52 = __hfma2(hm3, q3(v5),  a52);
            a62 = __hfma2(hm0, q0(v6),  a62); a62 = __hfma2(hm1, q1(v6),  a62);
            a62 = __hfma2(hm2, q2(v6),  a62); a62 = __hfma2(hm3, q3(v6),  a62);
            if (kq == 1 || kq == 3) {
                float2 f;
                f = __half22float2(es2); es += f.x + f.y; es2 = z2;
                f = __half22float2(e02); e0 += f.x + f.y; e02 = z2;
                f = __half22float2(e12); e1 += f.x + f.y; e12 = z2;
                f = __half22float2(e22); e2 += f.x + f.y; e22 = z2;
                f = __half22float2(a52); a5 += f.x + f.y; a52 = z2;
                f = __half22float2(a62); a6 += f.x + f.y; a62 = z2;
            }
        }
        es += sh0*e0 + sh1*e1 + sh2*e2;
        atomicAdd(&g_acc1[d*56 + lane], es);
        float C_ov  = __shfl_sync(0xffffffffu, a5, 24 + ov);
        float Dv_j1 = __shfl_sync(0xffffffffu, a6, j1*8 + ov);
        float Dv_j2 = __shfl_sync(0xffffffffu, a6, j2*8 + ov);
        if (lane < 24) {
            float shi  = (iidx == 0) ? sh0 : ((iidx == 1) ? sh1 : sh2);
            float shj1 = (j1 == 0) ? sh0 : ((j1 == 1) ? sh1 : sh2);
            float shj2 = (j2 == 0) ? sh0 : ((j2 == 1) ? sh1 : sh2);
            float ev = shi*C_ov + a5 + shj2*Dv_j1 - shj1*Dv_j2;
            atomicAdd(&g_acc1[d*56 + 32 + ov*3 + iidx], ev);
        }
    }
}

// ---- FUSED block2: LN(acc1) -> quad-interleaved fp16 tables -> LDS.128 edges ----
// A2 @0:   (m2>>2)*64 + ow*4 + (m2&3)
// B2 @256: i*256 + (m2>>2)*64 + ow*4 + (m2&3)
__global__ void __launch_bounds__(256) kE2f(const float* __restrict__ W2,
                                            const float* __restrict__ lng,
                                            const float* __restrict__ lnb)
{
    extern __shared__ __half2 smh[];   // 8 * 1024 half2 = 32768 B
    __shared__ float xs[8][32];
    __shared__ float xv[8][24];
    int t = threadIdx.x, warp = t >> 5, lane = t & 31;
    int nb = blockIdx.x * 8;
    ln_node(g_acc1, nb + warp, lane, lng, lnb, xs[warp], xv[warp]);
    __syncthreads();
    if (t < 256) {
        int m2 = t >> 4, ow = t & 15;
        const float* W0 = W2 + (2*m2)*640 + ow;
        const float* W1 = W2 + (2*m2+1)*640 + ow;
        float a0[8] = {0,0,0,0,0,0,0,0}, a1[8] = {0,0,0,0,0,0,0,0};
#pragma unroll
        for (int u = 0; u < 32; u++) {
            float w0 = W0[u*16], w1 = W1[u*16];
#pragma unroll
            for (int nn = 0; nn < 8; nn++) {
                a0[nn] += xs[nn][u] * w0;
                a1[nn] += xs[nn][u] * w1;
            }
        }
        int sidx = (m2 >> 2)*64 + ow*4 + (m2 & 3);
#pragma unroll
        for (int nn = 0; nn < 8; nn++)
            smh[nn*1024 + sidx] = __floats2half2_rn(a0[nn]*SA2, a1[nn]*SA2);
    }
    for (int idx = t; idx < 768; idx += 256) {
        int i = idx >> 8, r = idx & 255, m2 = r >> 4, ow = r & 15;
        const float* W0 = W2 + (2*m2)*640 + 512 + ow;
        const float* W1 = W2 + (2*m2+1)*640 + 512 + ow;
        float a0[8] = {0,0,0,0,0,0,0,0}, a1[8] = {0,0,0,0,0,0,0,0};
#pragma unroll
        for (int u = 0; u < 8; u++) {
            float w0 = W0[u*16], w1 = W1[u*16];
#pragma unroll
            for (int nn = 0; nn < 8; nn++) {
                a0[nn] += xv[nn][u*3 + i] * w0;
                a1[nn] += xv[nn][u*3 + i] * w1;
            }
        }
        int sidx = 256 + i*256 + (m2 >> 2)*64 + ow*4 + (m2 & 3);
#pragma unroll
        for (int nn = 0; nn < 8; nn++)
            smh[nn*1024 + sidx] = __floats2half2_rn(a0[nn]*SB2, a1[nn]*SB2);
    }
    __syncthreads();

    int r0 = g_rowptr[nb], r1 = g_rowptr[nb + 8];
    int sub = lane >> 4, ow = lane & 15;
    unsigned hmask = sub ? 0xffff0000u : 0x0000ffffu;
    const __half2 z2 = __float2half2_rn(0.f);
    for (int j = r0 + warp*2 + sub; j < r1; j += 16) {
        int s = g_psrc[j], d = g_pdst[j];
        const __half2* T = smh + (s - nb)*1024;
        __half2 hl2 = g_h2[j*16 + ow];
        float sh0 = g_sh[j*3+0], sh1 = g_sh[j*3+1], sh2 = g_sh[j*3+2];
        __half2 es2 = z2, e02 = z2, e12 = z2, e22 = z2;
        float es = 0.f, e0 = 0.f, e1 = 0.f, e2 = 0.f;
#pragma unroll
        for (int kq = 0; kq < 4; kq++) {
            __half2 hm0 = __shfl_sync(hmask, hl2, (sub << 4) + 4*kq);
            __half2 hm1 = __shfl_sync(hmask, hl2, (sub << 4) + 4*kq+1);
            __half2 hm2 = __shfl_sync(hmask, hl2, (sub << 4) + 4*kq+2);
            __half2 hm3 = __shfl_sync(hmask, hl2, (sub << 4) + 4*kq+3);
            uint4 va  = *reinterpret_cast<const uint4*>(T + kq*64 + ow*4);
            uint4 vb0 = *reinterpret_cast<const uint4*>(T + 256 + kq*64 + ow*4);
            uint4 vb1 = *reinterpret_cast<const uint4*>(T + 512 + kq*64 + ow*4);
            uint4 vb2 = *reinterpret_cast<const uint4*>(T + 768 + kq*64 + ow*4);
            es2 = __hfma2(hm0, q0(va),  es2); es2 = __hfma2(hm1, q1(va),  es2);
            es2 = __hfma2(hm2, q2(va),  es2); es2 = __hfma2(hm3, q3(va),  es2);
            e02 = __hfma2(hm0, q0(vb0), e02); e02 = __hfma2(hm1, q1(vb0), e02);
            e02 = __hfma2(hm2, q2(vb0), e02); e02 = __hfma2(hm3, q3(vb0), e02);
            e12 = __hfma2(hm0, q0(vb1), e12); e12 = __hfma2(hm1, q1(vb1), e12);
            e12 = __hfma2(hm2, q2(vb1), e12); e12 = __hfma2(hm3, q3(vb1), e12);
            e22 = __hfma2(hm0, q0(vb2), e22); e22 = __hfma2(hm1, q1(vb2), e22);
            e22 = __hfma2(hm2, q2(vb2), e22); e22 = __hfma2(hm3, q3(vb2), e22);
            if (kq == 1 || kq == 3) {
                float2 f;
                f = __half22float2(es2); es += f.x + f.y; es2 = z2;
                f = __half22float2(e02); e0 += f.x + f.y; e02 = z2;
                f = __half22float2(e12); e1 += f.x + f.y; e12 = z2;
                f = __half22float2(e22); e2 += f.x + f.y; e22 = z2;
            }
        }
        es += sh0*e0 + sh1*e1 + sh2*e2;
        atomicAdd(&g_acc2[d*16 + ow], es);
    }
}

// ---- final layernorm over 16 dims -> d_out ----
__global__ void kLN16(const float* __restrict__ g, const float* __restrict__ b,
                      float* __restrict__ out)
{
    int warp = threadIdx.x >> 5, lane = threadIdx.x & 31;
    int n = blockIdx.x * 8 + warp;
    float v = (lane < 16) ? g_acc2[n*16 + lane] * INV_SQRT8 : 0.f;
    float sum = v;
#pragma unroll
    for (int o = 16; o; o >>= 1) sum += __shfl_xor_sync(0xffffffffu, sum, o);
    float mean = sum * (1.f/16.f);
    float dd = (lane < 16) ? v - mean : 0.f;
    float sq = dd*dd;
#pragma unroll
    for (int o = 16; o; o >>= 1) sq += __shfl_xor_sync(0xffffffffu, sq, o);
    float rstd = rsqrtf(sq * (1.f/16.f) + 1e-5f);
    if (lane < 16) out[n*16 + lane] = dd * rstd * g[lane] + b[lane];
}

extern "C" void kernel_launch(void* const* d_in, const int* in_sizes, int n_in,
                              void* d_out, int out_size)
{
    (void)in_sizes; (void)n_in; (void)out_size;
    const float* pos  = (const float*)d_in[0];
    const int*   z    = (const int*)d_in[1];
    const int*   mol  = (const int*)d_in[2];
    const int*   src  = (const int*)d_in[3];
    const int*   dst  = (const int*)d_in[4];
    const float* Ez   = (const float*)d_in[5];
    const float* Em   = (const float*)d_in[6];
    const float* b0W1 = (const float*)d_in[7];
    const float* b0W2 = (const float*)d_in[8];
    const float* b0g  = (const float*)d_in[9];
    const float* b0b  = (const float*)d_in[10];
    const float* b1W1 = (const float*)d_in[11];
    const float* b1W2 = (const float*)d_in[12];
    const float* b1g  = (const float*)d_in[13];
    const float* b1b  = (const float*)d_in[14];
    const float* b2W1 = (const float*)d_in[15];
    const float* b2W2 = (const float*)d_in[16];
    const float* b2g  = (const float*)d_in[17];
    const float* b2b  = (const float*)d_in[18];
    float* out = (float*)d_out;

    static int attr_done = 0;
    if (!attr_done) {
        cudaFuncSetAttribute(kE1f, cudaFuncAttributeMaxDynamicSharedMemorySize, 8*2944*4);
        cudaFuncSetAttribute(kE2f, cudaFuncAttributeMaxDynamicSharedMemorySize, 8*1024*4);
        attr_done = 1;
    }

    kZeroP0  <<<232, 256>>>(Ez, Em, b0W2);
    kDeg     <<<NE/256, 256>>>(src);
    kScan    <<<1, 1024>>>();
    kHP      <<<NE/8, 256>>>(pos, src, dst, b0W1, b1W1, b2W1);
    kE0n     <<<NN/8, 256>>>(z, mol);
    kE1f     <<<NN/8, 512, 8*2944*4>>>(b1W2, b0g, b0b);
    kE2f     <<<NN/8, 256, 8*1024*4>>>(b2W2, b1g, b1b);
    kLN16    <<<NN/8, 256>>>(b2g, b2b, out);
}